// round 1
// baseline (speedup 1.0000x reference)
#include <cuda_runtime.h>

#define BB 4
#define LL 1024
#define VV 50257
#define DD 512
#define NBLK 128

// ---- scratch (no allocations allowed) ----
__device__ float g_xproj[BB * LL * DD];   // [B][L][D]
__device__ float g_hs[BB * LL * DD];      // [B][L][D]
__device__ float g_hbuf[2][BB * DD];      // double-buffered h
__device__ unsigned g_bar_count;
__device__ volatile unsigned g_bar_gen;

// =====================================================================
// K1: xproj[m][e] = sum_d emb[tok[m]][d] * Wx[e][d] + bx[e]
// M=4096, N=512, K=512.  64x64 tile, BK=16, 256 threads, 4x4/thread.
// =====================================================================
__global__ void k1_xproj(const int* __restrict__ tok, const float* __restrict__ emb,
                         const float* __restrict__ Wx, const float* __restrict__ bx)
{
    __shared__ float As[16][64];
    __shared__ float Bs[16][64];
    __shared__ int toks[64];
    const int m0 = blockIdx.y * 64;
    const int n0 = blockIdx.x * 64;
    const int tid = threadIdx.x;
    if (tid < 64) toks[tid] = tok[m0 + tid];
    __syncthreads();
    const int tm = tid >> 4, tn = tid & 15;
    const int lr = tid >> 2;          // 0..63
    const int lk = (tid & 3) << 2;    // 0,4,8,12
    const float* arow = emb + (size_t)toks[lr] * DD + lk;
    const float* brow = Wx + (size_t)(n0 + lr) * DD + lk;
    float acc[4][4] = {};
    for (int k0 = 0; k0 < DD; k0 += 16) {
        float4 av = *(const float4*)(arow + k0);
        float4 bv = *(const float4*)(brow + k0);
        __syncthreads();
        As[lk + 0][lr] = av.x; As[lk + 1][lr] = av.y;
        As[lk + 2][lr] = av.z; As[lk + 3][lr] = av.w;
        Bs[lk + 0][lr] = bv.x; Bs[lk + 1][lr] = bv.y;
        Bs[lk + 2][lr] = bv.z; Bs[lk + 3][lr] = bv.w;
        __syncthreads();
        #pragma unroll
        for (int k = 0; k < 16; k++) {
            float a[4], b[4];
            *(float4*)a = *(const float4*)&As[k][tm * 4];
            *(float4*)b = *(const float4*)&Bs[k][tn * 4];
            #pragma unroll
            for (int i = 0; i < 4; i++)
                #pragma unroll
                for (int j = 0; j < 4; j++)
                    acc[i][j] = fmaf(a[i], b[j], acc[i][j]);
        }
    }
    #pragma unroll
    for (int i = 0; i < 4; i++) {
        const int m = m0 + tm * 4 + i;
        #pragma unroll
        for (int j = 0; j < 4; j++) {
            const int e = n0 + tn * 4 + j;
            g_xproj[(size_t)m * DD + e] = acc[i][j] + bx[e];
        }
    }
}

// =====================================================================
// K2: sequential recurrence. 128 persistent blocks (all co-resident on
// 148 SMs), one grid barrier per timestep. Each warp owns one (e,b)
// output; its Wh row lives in registers for all 1024 steps.
// =====================================================================
__device__ __forceinline__ void grid_barrier()
{
    __syncthreads();
    if (threadIdx.x == 0) {
        __threadfence();
        const unsigned gen = g_bar_gen;
        if (atomicAdd(&g_bar_count, 1u) == NBLK - 1) {
            g_bar_count = 0;
            __threadfence();
            g_bar_gen = gen + 1;
        } else {
            while (g_bar_gen == gen) { }
        }
        __threadfence();
    }
    __syncthreads();
}

__global__ __launch_bounds__(512, 1) void k2_recur(const float* __restrict__ Wh,
                                                   const float* __restrict__ bh)
{
    __shared__ float sh[BB * DD];
    const int tid = threadIdx.x;
    const int lane = tid & 31;
    const int wid = tid >> 5;                  // 0..15
    const int b = wid & 3;
    const int e = blockIdx.x * 4 + (wid >> 2); // 0..511

    float wrow[16];
    #pragma unroll
    for (int k = 0; k < 16; k++)
        wrow[k] = Wh[(size_t)e * DD + lane + 32 * k];
    const float bias = bh[e];

    // t = 0: h_prev = 0
    if (lane == 0) {
        float v = fmaxf(bias + g_xproj[(size_t)(b * LL) * DD + e], 0.f);
        g_hbuf[0][b * DD + e] = v;
        g_hs[(size_t)(b * LL) * DD + e] = v;
        __threadfence();
    }

    for (int t = 1; t < LL; t++) {
        grid_barrier();
        // stage h_prev into smem (L2 load; L1 may be stale across barriers)
        const float4* src = (const float4*)g_hbuf[(t - 1) & 1];
        ((float4*)sh)[tid] = __ldcg(src + tid);
        __syncthreads();

        float acc = 0.f;
        #pragma unroll
        for (int k = 0; k < 16; k++)
            acc = fmaf(wrow[k], sh[b * DD + lane + 32 * k], acc);
        #pragma unroll
        for (int off = 16; off > 0; off >>= 1)
            acc += __shfl_xor_sync(0xffffffffu, acc, off);

        if (lane == 0) {
            float v = fmaxf(acc + bias + g_xproj[(size_t)(b * LL + t) * DD + e], 0.f);
            g_hbuf[t & 1][b * DD + e] = v;
            g_hs[(size_t)(b * LL + t) * DD + e] = v;
            __threadfence();
        }
    }
}

// =====================================================================
// K3: out[m][v] = sum_d hs[m][d] * Wo[v][d] + bo[v]
// M=4096, N=50257, K=512. 128x128 tile, BK=16, 256 threads, 8x8/thread.
// Inner product via packed fma.rn.f32x2 (2 FMAs/instr on sm_103a).
// =====================================================================
__device__ __forceinline__ unsigned long long pk2(float lo, float hi)
{
    unsigned long long r;
    asm("mov.b64 %0, {%1, %2};" : "=l"(r) : "f"(lo), "f"(hi));
    return r;
}
__device__ __forceinline__ void fma2(unsigned long long& d, unsigned long long a, unsigned long long b)
{
    asm("fma.rn.f32x2 %0, %1, %2, %0;" : "+l"(d) : "l"(a), "l"(b));
}
__device__ __forceinline__ float2 upk2(unsigned long long v)
{
    float2 r;
    asm("mov.b64 {%0, %1}, %2;" : "=f"(r.x), "=f"(r.y) : "l"(v));
    return r;
}

__global__ __launch_bounds__(256, 2) void k3_out(const float* __restrict__ Wo,
                                                 const float* __restrict__ bo,
                                                 float* __restrict__ out)
{
    __shared__ float As[16][128];
    __shared__ float Bs[16][128];
    const int m0 = blockIdx.x * 128;
    const int n0 = blockIdx.y * 128;
    const int tid = threadIdx.x;
    const int tm = tid >> 4, tn = tid & 15;
    const int lr = tid >> 2;          // 0..63
    const int lk = (tid & 3) << 2;    // 0,4,8,12
    const int v1 = n0 + lr, v2 = n0 + 64 + lr;
    const bool v1ok = v1 < VV, v2ok = v2 < VV;
    const float* a1p = g_hs + (size_t)(m0 + lr) * DD + lk;
    const float* a2p = g_hs + (size_t)(m0 + 64 + lr) * DD + lk;
    const float* b1p = Wo + (size_t)v1 * DD + lk;
    const float* b2p = Wo + (size_t)v2 * DD + lk;

    unsigned long long acc[8][4];
    #pragma unroll
    for (int i = 0; i < 8; i++)
        #pragma unroll
        for (int j = 0; j < 4; j++) acc[i][j] = 0ull;

    for (int k0 = 0; k0 < DD; k0 += 16) {
        float4 a1 = *(const float4*)(a1p + k0);
        float4 a2 = *(const float4*)(a2p + k0);
        float4 b1 = v1ok ? *(const float4*)(b1p + k0) : make_float4(0.f, 0.f, 0.f, 0.f);
        float4 b2 = v2ok ? *(const float4*)(b2p + k0) : make_float4(0.f, 0.f, 0.f, 0.f);
        __syncthreads();
        As[lk + 0][lr] = a1.x; As[lk + 1][lr] = a1.y;
        As[lk + 2][lr] = a1.z; As[lk + 3][lr] = a1.w;
        As[lk + 0][64 + lr] = a2.x; As[lk + 1][64 + lr] = a2.y;
        As[lk + 2][64 + lr] = a2.z; As[lk + 3][64 + lr] = a2.w;
        Bs[lk + 0][lr] = b1.x; Bs[lk + 1][lr] = b1.y;
        Bs[lk + 2][lr] = b1.z; Bs[lk + 3][lr] = b1.w;
        Bs[lk + 0][64 + lr] = b2.x; Bs[lk + 1][64 + lr] = b2.y;
        Bs[lk + 2][64 + lr] = b2.z; Bs[lk + 3][64 + lr] = b2.w;
        __syncthreads();
        #pragma unroll
        for (int k = 0; k < 16; k++) {
            float a[8], b[8];
            *(float4*)(a)     = *(const float4*)&As[k][tm * 8];
            *(float4*)(a + 4) = *(const float4*)&As[k][tm * 8 + 4];
            *(float4*)(b)     = *(const float4*)&Bs[k][tn * 8];
            *(float4*)(b + 4) = *(const float4*)&Bs[k][tn * 8 + 4];
            unsigned long long bp[4];
            #pragma unroll
            for (int j = 0; j < 4; j++) bp[j] = pk2(b[2 * j], b[2 * j + 1]);
            #pragma unroll
            for (int i = 0; i < 8; i++) {
                unsigned long long ap = pk2(a[i], a[i]);
                #pragma unroll
                for (int j = 0; j < 4; j++) fma2(acc[i][j], ap, bp[j]);
            }
        }
    }
    #pragma unroll
    for (int i = 0; i < 8; i++) {
        const int m = m0 + tm * 8 + i;
        float* orow = out + (size_t)m * VV;
        #pragma unroll
        for (int j = 0; j < 4; j++) {
            float2 r = upk2(acc[i][j]);
            const int v = n0 + tn * 8 + 2 * j;
            if (v < VV)     orow[v]     = r.x + bo[v];
            if (v + 1 < VV) orow[v + 1] = r.y + bo[v + 1];
        }
    }
}

// =====================================================================
extern "C" void kernel_launch(void* const* d_in, const int* in_sizes, int n_in,
                              void* d_out, int out_size)
{
    const int*   tok = (const int*)d_in[0];
    const float* emb = (const float*)d_in[1];
    const float* Wh  = (const float*)d_in[2];
    const float* bh  = (const float*)d_in[3];
    const float* Wx  = (const float*)d_in[4];
    const float* bx  = (const float*)d_in[5];
    const float* Wo  = (const float*)d_in[6];
    const float* bo  = (const float*)d_in[7];
    float* out = (float*)d_out;

    dim3 g1(DD / 64, (BB * LL) / 64);             // (8, 64)
    k1_xproj<<<g1, 256>>>(tok, emb, Wx, bx);

    k2_recur<<<NBLK, 512>>>(Wh, bh);

    dim3 g3((BB * LL) / 128, (VV + 127) / 128);   // (32, 393) — M fastest: Wo tile reused across the wave
    k3_out<<<g3, 256>>>(Wo, bo, out);
}

// round 4
// speedup vs baseline: 1.5907x; 1.5907x over previous
#include <cuda_runtime.h>
#include <cstdint>

#define BB 4
#define LL 1024
#define VV 50257
#define DD 512

// ---- scratch (no allocations allowed) ----
__device__ float g_xproj[BB * LL * DD];   // [B][L][D]
__device__ float g_hs[BB * LL * DD];      // [(b*L+t)][D]
__device__ float g_hbuf[2][BB * DD];      // double-buffered h
__device__ unsigned g_cnt2[BB];
__device__ volatile unsigned g_gen2[BB];

// =====================================================================
// helpers (base sm_103 ISA only — no 'a'-suffix features)
// =====================================================================
__device__ __forceinline__ uint32_t smem_u32(const void* p)
{
    uint32_t a;
    asm("{ .reg .u64 t; cvta.to.shared.u64 t, %1; cvt.u32.u64 %0, t; }" : "=r"(a) : "l"(p));
    return a;
}
#define SWZ128(x) ((x) ^ (((x) >> 3) & 0x70))

__device__ __forceinline__ void cpa16(uint32_t dst, const void* src, bool valid)
{
    asm volatile("cp.async.cg.shared.global [%0], [%1], 16, %2;"
                 :: "r"(dst), "l"(src), "r"(valid ? 16 : 0));
}
__device__ __forceinline__ void cpa_commit() { asm volatile("cp.async.commit_group;"); }
template <int N> __device__ __forceinline__ void cpa_wait() { asm volatile("cp.async.wait_group %0;" :: "n"(N)); }

__device__ __forceinline__ uint32_t to_tf32(float f)
{
    uint32_t r;
    asm("cvt.rna.tf32.f32 %0, %1;" : "=r"(r) : "f"(f));
    return r;
}
__device__ __forceinline__ void mma16n8k8(float* c, uint32_t a0, uint32_t a1, uint32_t a2, uint32_t a3,
                                          uint32_t b0, uint32_t b1)
{
    asm volatile("mma.sync.aligned.m16n8k8.row.col.f32.tf32.tf32.f32 "
                 "{%0,%1,%2,%3}, {%4,%5,%6,%7}, {%8,%9}, {%0,%1,%2,%3};"
                 : "+f"(c[0]), "+f"(c[1]), "+f"(c[2]), "+f"(c[3])
                 : "r"(a0), "r"(a1), "r"(a2), "r"(a3), "r"(b0), "r"(b1));
}

// =====================================================================
// K1: xproj = emb[tok] @ Wx^T + bx   (M=4096, N=512, K=512)
// =====================================================================
__global__ void k1_xproj(const int* __restrict__ tok, const float* __restrict__ emb,
                         const float* __restrict__ Wx, const float* __restrict__ bx)
{
    __shared__ float As[16][64];
    __shared__ float Bs[16][64];
    __shared__ int toks[64];
    const int m0 = blockIdx.y * 64;
    const int n0 = blockIdx.x * 64;
    const int tid = threadIdx.x;
    if (tid < 64) toks[tid] = tok[m0 + tid];
    __syncthreads();
    const int tm = tid >> 4, tn = tid & 15;
    const int lr = tid >> 2;
    const int lk = (tid & 3) << 2;
    const float* arow = emb + (size_t)toks[lr] * DD + lk;
    const float* brow = Wx + (size_t)(n0 + lr) * DD + lk;
    float acc[4][4] = {};
    for (int k0 = 0; k0 < DD; k0 += 16) {
        float4 av = *(const float4*)(arow + k0);
        float4 bv = *(const float4*)(brow + k0);
        __syncthreads();
        As[lk + 0][lr] = av.x; As[lk + 1][lr] = av.y;
        As[lk + 2][lr] = av.z; As[lk + 3][lr] = av.w;
        Bs[lk + 0][lr] = bv.x; Bs[lk + 1][lr] = bv.y;
        Bs[lk + 2][lr] = bv.z; Bs[lk + 3][lr] = bv.w;
        __syncthreads();
        #pragma unroll
        for (int k = 0; k < 16; k++) {
            float a[4], b[4];
            *(float4*)a = *(const float4*)&As[k][tm * 4];
            *(float4*)b = *(const float4*)&Bs[k][tn * 4];
            #pragma unroll
            for (int i = 0; i < 4; i++)
                #pragma unroll
                for (int j = 0; j < 4; j++)
                    acc[i][j] = fmaf(a[i], b[j], acc[i][j]);
        }
    }
    #pragma unroll
    for (int i = 0; i < 4; i++) {
        const int m = m0 + tm * 4 + i;
        #pragma unroll
        for (int j = 0; j < 4; j++) {
            const int e = n0 + tn * 4 + j;
            g_xproj[(size_t)m * DD + e] = acc[i][j] + bx[e];
        }
    }
}

// =====================================================================
// K2: recurrence. 4 independent batch chains, 32 blocks each, per-batch
// grid barrier. Each warp owns one e; Wh row in regs for all 1024 steps.
// =====================================================================
__device__ __forceinline__ void batch_barrier(int b)
{
    __syncthreads();
    if (threadIdx.x == 0) {
        __threadfence();
        const unsigned gen = g_gen2[b];
        if (atomicAdd(&g_cnt2[b], 1u) == 31u) {
            g_cnt2[b] = 0;
            __threadfence();
            g_gen2[b] = gen + 1;
        } else {
            while (g_gen2[b] == gen) { }
        }
        __threadfence();
    }
    __syncthreads();
}

__global__ __launch_bounds__(512, 1) void k2_recur(const float* __restrict__ Wh,
                                                   const float* __restrict__ bh)
{
    __shared__ float sh[DD];
    const int tid = threadIdx.x;
    const int lane = tid & 31;
    const int wid = tid >> 5;              // 0..15
    const int b = blockIdx.x >> 5;         // batch
    const int g = blockIdx.x & 31;
    const int e = g * 16 + wid;            // 0..511

    float wrow[16];
    #pragma unroll
    for (int k = 0; k < 16; k++)
        wrow[k] = Wh[(size_t)e * DD + lane + 32 * k];
    const float bias = bh[e];

    if (lane == 0) {
        float v = fmaxf(bias + g_xproj[(size_t)(b * LL) * DD + e], 0.f);
        g_hbuf[0][b * DD + e] = v;
        g_hs[(size_t)(b * LL) * DD + e] = v;
        __threadfence();
    }

    for (int t = 1; t < LL; t++) {
        batch_barrier(b);
        if (tid < 128)
            ((float4*)sh)[tid] = __ldcg((const float4*)(g_hbuf[(t - 1) & 1] + b * DD) + tid);
        __syncthreads();

        float acc = 0.f;
        #pragma unroll
        for (int k = 0; k < 16; k++)
            acc = fmaf(wrow[k], sh[lane + 32 * k], acc);
        #pragma unroll
        for (int off = 16; off > 0; off >>= 1)
            acc += __shfl_xor_sync(0xffffffffu, acc, off);

        if (lane == 0) {
            float v = fmaxf(acc + bias + g_xproj[(size_t)(b * LL + t) * DD + e], 0.f);
            g_hbuf[t & 1][b * DD + e] = v;
            g_hs[(size_t)(b * LL + t) * DD + e] = v;
            __threadfence();
        }
    }
}

// =====================================================================
// K3: out = hs @ Wo^T + bo  (M=4096, N=50257, K=512)
// mma.sync m16n8k8 tf32. CTA 128x128, BK=32 floats (128B rows, SW128
// swizzle -> conflict-free fragment LDS), 3-stage cp.async pipeline.
// Warps 2(m) x 4(n): each warp 64x32, 64 fp32 accums/thread.
// NOTE: VV=50257 is ODD -> out rows are only 4B-aligned. All output
// stores must be scalar 32-bit (float2/float4 STG traps on odd rows).
// =====================================================================
#define K3_BM 128
#define K3_BN 128
#define K3_BK 32
#define K3_NCH (DD / K3_BK)                   // 16
#define K3_STAGE_FLOATS ((K3_BM + K3_BN) * K3_BK)   // 8192 floats = 32KB
#define K3_STAGES 3
#define K3_SMEM_BYTES (K3_STAGES * K3_STAGE_FLOATS * 4)  // 98304

__global__ __launch_bounds__(256, 1)
void k3_mma(const float* __restrict__ Wo, const float* __restrict__ bo,
            float* __restrict__ out)
{
    extern __shared__ __align__(1024) float sm[];
    const uint32_t smem_base = smem_u32(sm);
    const int tid = threadIdx.x;
    const int wid = tid >> 5;
    const int lane = tid & 31;
    const int m0 = blockIdx.x * K3_BM;
    const int n0 = blockIdx.y * K3_BN;
    const int warp_m = (wid & 1) * 64;
    const int warp_n = (wid >> 1) * 32;

    // ---- loader: 16B segs, 128B-swizzled rows; A rows [0,128), B rows [0,128) in B region
    const int seg = tid & 7;       // 16B segment within 128B row
    const int r0 = tid >> 3;       // 0..31
    auto issue = [&](int c, int s) {
        const uint32_t abase = smem_base + s * (K3_STAGE_FLOATS * 4);
        const uint32_t bbase = abase + K3_BM * 128;
        const float* asrc = g_hs + (size_t)(m0 + r0) * DD + c * K3_BK + seg * 4;
        #pragma unroll
        for (int i = 0; i < 4; i++) {
            const int row = r0 + 32 * i;
            cpa16(abase + SWZ128(row * 128 + seg * 16), asrc + (size_t)32 * i * DD, true);
        }
        #pragma unroll
        for (int i = 0; i < 4; i++) {
            const int row = r0 + 32 * i;
            const int v = n0 + row;
            const float* bsrc = Wo + (size_t)(v < VV ? v : 0) * DD + c * K3_BK + seg * 4;
            cpa16(bbase + SWZ128(row * 128 + seg * 16), bsrc, v < VV);
        }
        cpa_commit();
    };

    issue(0, 0);
    issue(1, 1);

    // fragment addressing: float idx = row*32 + (col ^ 4*(row&7))
    const int cx = (lane >> 2) * 4;             // (row&7)*4, same for all frags
    int aoff[4], boff[4];
    #pragma unroll
    for (int f = 0; f < 4; f++) {
        aoff[f] = (warp_m + f * 16 + (lane >> 2)) * 32;
        boff[f] = (warp_n + f * 8 + (lane >> 2)) * 32;
    }

    float acc[4][4][4];
    #pragma unroll
    for (int i = 0; i < 4; i++)
        #pragma unroll
        for (int j = 0; j < 4; j++)
            #pragma unroll
            for (int q = 0; q < 4; q++) acc[i][j][q] = 0.f;

    for (int c = 0; c < K3_NCH; c++) {
        if (c == K3_NCH - 1) cpa_wait<0>(); else cpa_wait<1>();
        __syncthreads();
        if (c + 2 < K3_NCH) issue(c + 2, (c + 2) % K3_STAGES);

        const float* Ast = sm + (c % K3_STAGES) * K3_STAGE_FLOATS;
        const float* Bst = Ast + K3_BM * K3_BK;

        #pragma unroll
        for (int ks = 0; ks < 4; ks++) {
            const int c0 = ks * 8 + (lane & 3);
            const int cA0 = c0 ^ cx;
            const int cA1 = (c0 + 4) ^ cx;

            uint32_t a[4][4];
            #pragma unroll
            for (int fm = 0; fm < 4; fm++) {
                a[fm][0] = to_tf32(Ast[aoff[fm] + cA0]);
                a[fm][1] = to_tf32(Ast[aoff[fm] + 256 + cA0]);
                a[fm][2] = to_tf32(Ast[aoff[fm] + cA1]);
                a[fm][3] = to_tf32(Ast[aoff[fm] + 256 + cA1]);
            }
            uint32_t b[4][2];
            #pragma unroll
            for (int fn = 0; fn < 4; fn++) {
                b[fn][0] = to_tf32(Bst[boff[fn] + cA0]);
                b[fn][1] = to_tf32(Bst[boff[fn] + cA1]);
            }
            #pragma unroll
            for (int fm = 0; fm < 4; fm++)
                #pragma unroll
                for (int fn = 0; fn < 4; fn++)
                    mma16n8k8(acc[fm][fn], a[fm][0], a[fm][1], a[fm][2], a[fm][3],
                              b[fn][0], b[fn][1]);
        }
    }

    // ---- epilogue: scalar 32-bit stores ONLY (odd VV => odd-row bases
    // are not 8B-aligned). Frag layout: c0=(r,2c) c1=(r,2c+1) c2=(r+8,2c) c3=(r+8,2c+1)
    #pragma unroll
    for (int fm = 0; fm < 4; fm++) {
        const int m = m0 + warp_m + fm * 16 + (lane >> 2);
        float* orow0 = out + (size_t)m * VV;
        float* orow1 = out + (size_t)(m + 8) * VV;
        #pragma unroll
        for (int fn = 0; fn < 4; fn++) {
            const int v = n0 + warp_n + fn * 8 + 2 * (lane & 3);
            if (v < VV) {
                const float b0 = bo[v];
                orow0[v] = acc[fm][fn][0] + b0;
                orow1[v] = acc[fm][fn][2] + b0;
            }
            if (v + 1 < VV) {
                const float b1 = bo[v + 1];
                orow0[v + 1] = acc[fm][fn][1] + b1;
                orow1[v + 1] = acc[fm][fn][3] + b1;
            }
        }
    }
}

// =====================================================================
extern "C" void kernel_launch(void* const* d_in, const int* in_sizes, int n_in,
                              void* d_out, int out_size)
{
    const int*   tok = (const int*)d_in[0];
    const float* emb = (const float*)d_in[1];
    const float* Wh  = (const float*)d_in[2];
    const float* bh  = (const float*)d_in[3];
    const float* Wx  = (const float*)d_in[4];
    const float* bx  = (const float*)d_in[5];
    const float* Wo  = (const float*)d_in[6];
    const float* bo  = (const float*)d_in[7];
    float* out = (float*)d_out;

    dim3 g1(DD / 64, (BB * LL) / 64);
    k1_xproj<<<g1, 256>>>(tok, emb, Wx, bx);

    k2_recur<<<128, 512>>>(Wh, bh);

    cudaFuncSetAttribute(k3_mma, cudaFuncAttributeMaxDynamicSharedMemorySize, K3_SMEM_BYTES);
    dim3 g3((BB * LL) / K3_BM, (VV + K3_BN - 1) / K3_BN);   // (32, 393), M fastest
    k3_mma<<<g3, 256, K3_SMEM_BYTES>>>(Wo, bo, out);
}

// round 5
// speedup vs baseline: 3.6332x; 2.2840x over previous
#include <cuda_runtime.h>
#include <cuda_fp16.h>
#include <cstdint>

#define BB 4
#define LL 1024
#define VV 50257
#define DD 512

// ---- scratch (no allocations allowed) ----
__device__ float  g_xproj[BB * LL * DD];          // [b*L+t][D] fp32
__device__ __half g_hs_h[BB * LL * DD];           // [b*L+t][D] fp16 (K3 A operand)
__device__ __half g_wo_h[(size_t)VV * DD];        // Wo as fp16

// =====================================================================
// helpers (base sm_103 ISA only — no 'a'-suffix features)
// =====================================================================
__device__ __forceinline__ uint32_t smem_u32(const void* p)
{
    uint32_t a;
    asm("{ .reg .u64 t; cvta.to.shared.u64 t, %1; cvt.u32.u64 %0, t; }" : "=r"(a) : "l"(p));
    return a;
}
#define SWZ128(x) ((x) ^ (((x) >> 3) & 0x70))

__device__ __forceinline__ void cpa16(uint32_t dst, const void* src, bool valid)
{
    asm volatile("cp.async.cg.shared.global [%0], [%1], 16, %2;"
                 :: "r"(dst), "l"(src), "r"(valid ? 16 : 0));
}
__device__ __forceinline__ void cpa_commit() { asm volatile("cp.async.commit_group;"); }
template <int N> __device__ __forceinline__ void cpa_wait() { asm volatile("cp.async.wait_group %0;" :: "n"(N)); }

__device__ __forceinline__ void ldm4(uint32_t* r, uint32_t addr)
{
    asm volatile("ldmatrix.sync.aligned.m8n8.x4.shared.b16 {%0,%1,%2,%3}, [%4];"
                 : "=r"(r[0]), "=r"(r[1]), "=r"(r[2]), "=r"(r[3]) : "r"(addr));
}
__device__ __forceinline__ void mma16816(float* c, const uint32_t* a, uint32_t b0, uint32_t b1)
{
    asm volatile("mma.sync.aligned.m16n8k16.row.col.f32.f16.f16.f32 "
                 "{%0,%1,%2,%3}, {%4,%5,%6,%7}, {%8,%9}, {%0,%1,%2,%3};"
                 : "+f"(c[0]), "+f"(c[1]), "+f"(c[2]), "+f"(c[3])
                 : "r"(a[0]), "r"(a[1]), "r"(a[2]), "r"(a[3]), "r"(b0), "r"(b1));
}
__device__ __forceinline__ void st_cluster_f32(uint32_t laddr, uint32_t rank, float v)
{
    uint32_t ra;
    asm volatile("mapa.shared::cluster.u32 %0, %1, %2;" : "=r"(ra) : "r"(laddr), "r"(rank));
    asm volatile("st.shared::cluster.f32 [%0], %1;" :: "r"(ra), "f"(v) : "memory");
}
#define CLUSTER_SYNC() do { \
    asm volatile("barrier.cluster.arrive.aligned;" ::: "memory"); \
    asm volatile("barrier.cluster.wait.aligned;" ::: "memory"); } while (0)

// =====================================================================
// K0: Wo fp32 -> fp16
// =====================================================================
__global__ void k0_conv(const float* __restrict__ Wo)
{
    const size_t i4 = (size_t)blockIdx.x * blockDim.x + threadIdx.x;
    if (i4 * 4 >= (size_t)VV * DD) return;
    float4 v = *(const float4*)(Wo + i4 * 4);
    __half2 p0 = __floats2half2_rn(v.x, v.y);
    __half2 p1 = __floats2half2_rn(v.z, v.w);
    __half2* dst = (__half2*)(g_wo_h + i4 * 4);
    dst[0] = p0;
    dst[1] = p1;
}

// =====================================================================
// K1: xproj = emb[tok] @ Wx^T + bx   (M=4096, N=512, K=512)
// =====================================================================
__global__ void k1_xproj(const int* __restrict__ tok, const float* __restrict__ emb,
                         const float* __restrict__ Wx, const float* __restrict__ bx)
{
    __shared__ float As[16][64];
    __shared__ float Bs[16][64];
    __shared__ int toks[64];
    const int m0 = blockIdx.y * 64;
    const int n0 = blockIdx.x * 64;
    const int tid = threadIdx.x;
    if (tid < 64) toks[tid] = tok[m0 + tid];
    __syncthreads();
    const int tm = tid >> 4, tn = tid & 15;
    const int lr = tid >> 2;
    const int lk = (tid & 3) << 2;
    const float* arow = emb + (size_t)toks[lr] * DD + lk;
    const float* brow = Wx + (size_t)(n0 + lr) * DD + lk;
    float acc[4][4] = {};
    for (int k0 = 0; k0 < DD; k0 += 16) {
        float4 av = *(const float4*)(arow + k0);
        float4 bv = *(const float4*)(brow + k0);
        __syncthreads();
        As[lk + 0][lr] = av.x; As[lk + 1][lr] = av.y;
        As[lk + 2][lr] = av.z; As[lk + 3][lr] = av.w;
        Bs[lk + 0][lr] = bv.x; Bs[lk + 1][lr] = bv.y;
        Bs[lk + 2][lr] = bv.z; Bs[lk + 3][lr] = bv.w;
        __syncthreads();
        #pragma unroll
        for (int k = 0; k < 16; k++) {
            float a[4], b[4];
            *(float4*)a = *(const float4*)&As[k][tm * 4];
            *(float4*)b = *(const float4*)&Bs[k][tn * 4];
            #pragma unroll
            for (int i = 0; i < 4; i++)
                #pragma unroll
                for (int j = 0; j < 4; j++)
                    acc[i][j] = fmaf(a[i], b[j], acc[i][j]);
        }
    }
    #pragma unroll
    for (int i = 0; i < 4; i++) {
        const int m = m0 + tm * 4 + i;
        #pragma unroll
        for (int j = 0; j < 4; j++) {
            const int e = n0 + tn * 4 + j;
            g_xproj[(size_t)m * DD + e] = acc[i][j] + bx[e];
        }
    }
}

// =====================================================================
// K2: recurrence with 8-CTA clusters (one cluster per batch).
// 512 thr/CTA, 16 warps, 4 e's per warp (CTA owns 64 e's).
// h broadcast to all peers' smem via st.shared::cluster, one
// barrier.cluster per step. Double-buffered smem h.
// =====================================================================
__global__ __launch_bounds__(512, 1) __cluster_dims__(8, 1, 1)
void k2_recur(const float* __restrict__ Wh, const float* __restrict__ bh)
{
    __shared__ float sh[2][DD];
    const int tid = threadIdx.x;
    const int lane = tid & 31;
    const int w = tid >> 5;                 // 0..15
    const int batch = blockIdx.x >> 3;
    const int crank = blockIdx.x & 7;
    const int e_base = crank * 64 + w * 4;  // this warp's 4 e's

    // weights: wrow[j][kk] = Wh[e][lane + 32*kk]  (coalesced per (j,kk))
    float wrow[4][16];
    float bias[4];
    #pragma unroll
    for (int j = 0; j < 4; j++) {
        bias[j] = bh[e_base + j];
        #pragma unroll
        for (int kk = 0; kk < 16; kk++)
            wrow[j][kk] = Wh[(size_t)(e_base + j) * DD + lane + 32 * kk];
    }
    const float* xp = g_xproj + (size_t)batch * LL * DD;

    // t = 0: h_prev = 0
    {
        float v[4];
        #pragma unroll
        for (int j = 0; j < 4; j++)
            v[j] = fmaxf(bias[j] + __ldcg(xp + e_base + j), 0.f);
        if (lane < 8) {
            #pragma unroll
            for (int j = 0; j < 4; j++)
                st_cluster_f32(smem_u32(&sh[0][e_base + j]), lane, v[j]);
        }
        if (lane == 8) {
            __half2* dst = (__half2*)(g_hs_h + (size_t)(batch * LL) * DD + e_base);
            dst[0] = __floats2half2_rn(v[0], v[1]);
            dst[1] = __floats2half2_rn(v[2], v[3]);
        }
    }

    for (int t = 1; t < LL; t++) {
        CLUSTER_SYNC();   // prior step's peer stores now visible

        float xv[4];
        #pragma unroll
        for (int j = 0; j < 4; j++)
            xv[j] = __ldcg(xp + (size_t)t * DD + e_base + j);

        float hreg[16];
        const float* hb = sh[(t - 1) & 1];
        #pragma unroll
        for (int kk = 0; kk < 16; kk++)
            hreg[kk] = hb[lane + 32 * kk];

        float acc[4] = {0.f, 0.f, 0.f, 0.f};
        #pragma unroll
        for (int kk = 0; kk < 16; kk++)
            #pragma unroll
            for (int j = 0; j < 4; j++)
                acc[j] = fmaf(wrow[j][kk], hreg[kk], acc[j]);

        #pragma unroll
        for (int off = 16; off > 0; off >>= 1)
            #pragma unroll
            for (int j = 0; j < 4; j++)
                acc[j] += __shfl_xor_sync(0xffffffffu, acc[j], off);

        float v[4];
        #pragma unroll
        for (int j = 0; j < 4; j++)
            v[j] = fmaxf(acc[j] + bias[j] + xv[j], 0.f);

        if (t < LL - 1 && lane < 8) {
            #pragma unroll
            for (int j = 0; j < 4; j++)
                st_cluster_f32(smem_u32(&sh[t & 1][e_base + j]), lane, v[j]);
        }
        if (lane == 8) {
            __half2* dst = (__half2*)(g_hs_h + (size_t)(batch * LL + t) * DD + e_base);
            dst[0] = __floats2half2_rn(v[0], v[1]);
            dst[1] = __floats2half2_rn(v[2], v[3]);
        }
    }
}

// =====================================================================
// K3: out = hs @ Wo^T + bo  (M=4096, N=50257, K=512) — fp16 HMMA.
// CTA 128x128, BK=64 halves (128B rows, SW128), 3-stage cp.async,
// ldmatrix fragment loads, warps 2(m) x 4(n) => warp tile 64x32.
// VV odd => scalar fp32 output stores only.
// =====================================================================
#define K3_BM 128
#define K3_BN 128
#define K3_BKH 64
#define K3_NCH (DD / K3_BKH)                     // 8
#define K3_STAGE_BYTES ((K3_BM + K3_BN) * 128)   // 32768
#define K3_STAGES 3
#define K3_SMEM_BYTES (K3_STAGES * K3_STAGE_BYTES)  // 98304

__global__ __launch_bounds__(256, 2)
void k3_mma(const float* __restrict__ bo, float* __restrict__ out)
{
    extern __shared__ __align__(1024) char smc[];
    const uint32_t smem_base = smem_u32(smc);
    const int tid = threadIdx.x;
    const int wid = tid >> 5;
    const int lane = tid & 31;
    const int m0 = blockIdx.x * K3_BM;
    const int n0 = blockIdx.y * K3_BN;
    const int warp_m = (wid & 1) * 64;
    const int warp_n = (wid >> 1) * 32;

    // ---- loader: 16B segs, swizzled 128B rows
    const int seg = tid & 7;
    const int r0 = tid >> 3;      // 0..31
    auto issue = [&](int c, int s) {
        const uint32_t abase = smem_base + s * K3_STAGE_BYTES;
        const uint32_t bbase = abase + K3_BM * 128;
        const __half* asrc = g_hs_h + (size_t)(m0 + r0) * DD + c * K3_BKH + seg * 8;
        #pragma unroll
        for (int i = 0; i < 4; i++) {
            const int row = r0 + 32 * i;
            cpa16(abase + SWZ128(row * 128 + seg * 16), asrc + (size_t)32 * i * DD, true);
        }
        #pragma unroll
        for (int i = 0; i < 4; i++) {
            const int row = r0 + 32 * i;
            const int v = n0 + row;
            const __half* bsrc = g_wo_h + (size_t)(v < VV ? v : 0) * DD + c * K3_BKH + seg * 8;
            cpa16(bbase + SWZ128(row * 128 + seg * 16), bsrc, v < VV);
        }
        cpa_commit();
    };

    issue(0, 0);
    issue(1, 1);

    // ldmatrix lane geometry (precomputed row / col parts)
    int arow[4], axor[4];
    #pragma unroll
    for (int f = 0; f < 4; f++) {
        const int row = warp_m + f * 16 + (lane & 15);
        arow[f] = row * 128;
        axor[f] = (row & 7) * 16;
    }
    const int acol0 = (lane >> 4) * 16;     // +32*ks later
    int brow[2], bxor[2];
    #pragma unroll
    for (int g = 0; g < 2; g++) {
        const int nr = warp_n + g * 16 + ((lane & 16) >> 1) + (lane & 7);
        brow[g] = nr * 128;
        bxor[g] = (nr & 7) * 16;
    }
    const int bcol0 = ((lane >> 3) & 1) * 16;  // +32*ks later

    float acc[4][4][4];
    #pragma unroll
    for (int i = 0; i < 4; i++)
        #pragma unroll
        for (int j = 0; j < 4; j++)
            #pragma unroll
            for (int q = 0; q < 4; q++) acc[i][j][q] = 0.f;

    for (int c = 0; c < K3_NCH; c++) {
        if (c == K3_NCH - 1) cpa_wait<0>(); else cpa_wait<1>();
        __syncthreads();
        if (c + 2 < K3_NCH) issue(c + 2, (c + 2) % K3_STAGES);

        const uint32_t Ast = smem_base + (c % K3_STAGES) * K3_STAGE_BYTES;
        const uint32_t Bst = Ast + K3_BM * 128;

        #pragma unroll
        for (int ks = 0; ks < 4; ks++) {
            uint32_t A[4][4];
            #pragma unroll
            for (int f = 0; f < 4; f++)
                ldm4(A[f], Ast + arow[f] + (((acol0 + 32 * ks)) ^ axor[f]));
            uint32_t Bf[2][4];
            #pragma unroll
            for (int g = 0; g < 2; g++)
                ldm4(Bf[g], Bst + brow[g] + (((bcol0 + 32 * ks)) ^ bxor[g]));
            #pragma unroll
            for (int fm = 0; fm < 4; fm++) {
                #pragma unroll
                for (int g = 0; g < 2; g++) {
                    mma16816(acc[fm][2 * g],     A[fm], Bf[g][0], Bf[g][1]);
                    mma16816(acc[fm][2 * g + 1], A[fm], Bf[g][2], Bf[g][3]);
                }
            }
        }
        __syncthreads();
    }

    // ---- epilogue: scalar 32-bit stores (VV odd => rows only 4B-aligned)
    #pragma unroll
    for (int fm = 0; fm < 4; fm++) {
        const int m = m0 + warp_m + fm * 16 + (lane >> 2);
        float* orow0 = out + (size_t)m * VV;
        float* orow1 = out + (size_t)(m + 8) * VV;
        #pragma unroll
        for (int fn = 0; fn < 4; fn++) {
            const int v = n0 + warp_n + fn * 8 + 2 * (lane & 3);
            if (v < VV) {
                const float b0 = bo[v];
                orow0[v] = acc[fm][fn][0] + b0;
                orow1[v] = acc[fm][fn][2] + b0;
            }
            if (v + 1 < VV) {
                const float b1 = bo[v + 1];
                orow0[v + 1] = acc[fm][fn][1] + b1;
                orow1[v + 1] = acc[fm][fn][3] + b1;
            }
        }
    }
}

// =====================================================================
extern "C" void kernel_launch(void* const* d_in, const int* in_sizes, int n_in,
                              void* d_out, int out_size)
{
    const int*   tok = (const int*)d_in[0];
    const float* emb = (const float*)d_in[1];
    const float* Wh  = (const float*)d_in[2];
    const float* bh  = (const float*)d_in[3];
    const float* Wx  = (const float*)d_in[4];
    const float* bx  = (const float*)d_in[5];
    const float* Wo  = (const float*)d_in[6];
    const float* bo  = (const float*)d_in[7];
    float* out = (float*)d_out;

    const size_t n4 = ((size_t)VV * DD) / 4;
    k0_conv<<<(unsigned)((n4 + 255) / 256), 256>>>(Wo);

    dim3 g1(DD / 64, (BB * LL) / 64);
    k1_xproj<<<g1, 256>>>(tok, emb, Wx, bx);

    k2_recur<<<32, 512>>>(Wh, bh);   // 4 clusters of 8 CTAs

    cudaFuncSetAttribute(k3_mma, cudaFuncAttributeMaxDynamicSharedMemorySize, K3_SMEM_BYTES);
    dim3 g3((BB * LL) / K3_BM, (VV + K3_BN - 1) / K3_BN);   // (32, 393), M fastest
    k3_mma<<<g3, 256, K3_SMEM_BYTES>>>(bo, out);
}